// round 16
// baseline (speedup 1.0000x reference)
#include <cuda_runtime.h>
#include <cstdint>

#define B_  2
#define C_  512
#define NH  8
#define D_  64
#define S_  2304
#define QSCALE 0.1803368801f   // 0.125 * log2(e); attn uses exp2
#define QT  128
#define NCH (S_ / 64)

// ---------------------------------------------------------------------------
__device__ __forceinline__ float tf32r(float f) {
    unsigned r; asm("cvt.rna.tf32.f32 %0, %1;" : "=r"(r) : "f"(f));
    return __uint_as_float(r);
}
__device__ __forceinline__ void mma_tf32(float c[4],
                                         float a0, float a1, float a2, float a3,
                                         float b0, float b1) {
    asm volatile(
        "mma.sync.aligned.m16n8k8.row.col.f32.tf32.tf32.f32 "
        "{%0,%1,%2,%3}, {%4,%5,%6,%7}, {%8,%9}, {%0,%1,%2,%3};\n"
        : "+f"(c[0]), "+f"(c[1]), "+f"(c[2]), "+f"(c[3])
        : "r"(__float_as_uint(a0)), "r"(__float_as_uint(a1)),
          "r"(__float_as_uint(a2)), "r"(__float_as_uint(a3)),
          "r"(__float_as_uint(b0)), "r"(__float_as_uint(b1)));
}
__device__ __forceinline__ void cpasync16(uint32_t s, const void* g) {
    asm volatile("cp.async.cg.shared.global [%0], [%1], 16;" :: "r"(s), "l"(g));
}
#define CP_COMMIT() asm volatile("cp.async.commit_group;" ::: "memory")
#define CP_WAIT0()  asm volatile("cp.async.wait_group 0;" ::: "memory")

// Scratch ------------------------------------------------------------------
__device__ float g_q[B_ * NH * S_ * D_];    // [bn][s][d]  (QSCALE folded)
__device__ float g_k[B_ * NH * S_ * D_];    // [bn][s][d]
__device__ float g_v[B_ * NH * D_ * S_];    // [bn][d][s]
__device__ float g_attn[B_ * S_ * NH * D_]; // [b][s][n*64+d]

// ===========================================================================
// FUSED QKV projection: one CTA computes Q,K,V for a (bn, 64-s) tile.
// x-tile loaded ONCE per chunk; B-fragments reused across the 3 outputs.
// CTA 64d x 64s x {Q,K,V}; warp 32x32; k-chunk 32.  grid (36, 16), block 128.
// Smem: As[3][64][36] (27.6KB) | Bs[32][72] (9.2KB); Ts overlays As.
// ===========================================================================
__global__ __launch_bounds__(128) void proj_kernel(
    const float* __restrict__ x,
    const float* __restrict__ Wq, const float* __restrict__ bq,
    const float* __restrict__ Wk, const float* __restrict__ bk,
    const float* __restrict__ Wv, const float* __restrict__ bv)
{
    __shared__ float As[3][64][36];
    __shared__ float Bs[32][72];
    float (*Ts)[68] = (float (*)[68])As;     // epilogue staging [s][d]

    const int bn = blockIdx.y;
    const int b  = bn >> 3, n = bn & 7;
    const int s0 = blockIdx.x * 64;

    const int tid  = threadIdx.x;
    const int wid  = tid >> 5, lane = tid & 31;
    const int gid  = lane >> 2, tig = lane & 3;
    const int wm   = wid >> 1, wn = wid & 1;

    const float* xb = x + (size_t)b * C_ * S_ + s0;
    const float* Wp[3] = { Wq + n * D_ * C_, Wk + n * D_ * C_, Wv + n * D_ * C_ };
    const float* bp[3] = { bq + n * D_, bk + n * D_, bv + n * D_ };

    float Cacc[3][2][4][4] = {};

    for (int k0 = 0; k0 < C_; k0 += 32) {
        // x tile once (512 float4)
        #pragma unroll
        for (int r = 0; r < 4; r++) {
            int i4 = tid + r * 128;
            int cc = i4 >> 4, s4 = (i4 & 15) * 4;
            float4 v = *(const float4*)&xb[(size_t)(k0 + cc) * S_ + s4];
            Bs[cc][s4]     = tf32r(v.x); Bs[cc][s4 + 1] = tf32r(v.y);
            Bs[cc][s4 + 2] = tf32r(v.z); Bs[cc][s4 + 3] = tf32r(v.w);
        }
        // 3 W tiles (512 float4 each)
        #pragma unroll
        for (int p = 0; p < 3; p++) {
            #pragma unroll
            for (int r = 0; r < 4; r++) {
                int i4 = tid + r * 128;
                int dd = i4 >> 3, c4 = (i4 & 7) * 4;
                float4 v = *(const float4*)&Wp[p][dd * C_ + k0 + c4];
                As[p][dd][c4]     = tf32r(v.x); As[p][dd][c4 + 1] = tf32r(v.y);
                As[p][dd][c4 + 2] = tf32r(v.z); As[p][dd][c4 + 3] = tf32r(v.w);
            }
        }
        __syncthreads();

        #pragma unroll
        for (int kk = 0; kk < 32; kk += 8) {
            float b0[4], b1[4];
            #pragma unroll
            for (int j = 0; j < 4; j++) {
                int col = wn * 32 + j * 8 + gid;
                b0[j] = Bs[kk + tig][col];
                b1[j] = Bs[kk + tig + 4][col];
            }
            #pragma unroll
            for (int p = 0; p < 3; p++) {
                float a[2][4];
                #pragma unroll
                for (int i = 0; i < 2; i++) {
                    int row = wm * 32 + i * 16;
                    a[i][0] = As[p][row + gid][kk + tig];
                    a[i][1] = As[p][row + gid + 8][kk + tig];
                    a[i][2] = As[p][row + gid][kk + tig + 4];
                    a[i][3] = As[p][row + gid + 8][kk + tig + 4];
                }
                #pragma unroll
                for (int j = 0; j < 4; j++)
                    #pragma unroll
                    for (int i = 0; i < 2; i++)
                        mma_tf32(Cacc[p][i][j], a[i][0], a[i][1], a[i][2], a[i][3],
                                 b0[j], b1[j]);
            }
        }
        __syncthreads();
    }

    // ---- V epilogue: direct [d][s] float2 (no smem needed)
    {
        float* g = g_v + (size_t)bn * D_ * S_;
        #pragma unroll
        for (int i = 0; i < 2; i++) {
            int r0 = wm * 32 + i * 16 + gid;
            float bi0 = bp[2][r0], bi1 = bp[2][r0 + 8];
            #pragma unroll
            for (int j = 0; j < 4; j++) {
                int col = s0 + wn * 32 + j * 8 + 2 * tig;
                *(float2*)&g[(size_t)r0 * S_ + col] =
                    make_float2(Cacc[2][i][j][0] + bi0, Cacc[2][i][j][1] + bi0);
                *(float2*)&g[(size_t)(r0 + 8) * S_ + col] =
                    make_float2(Cacc[2][i][j][2] + bi1, Cacc[2][i][j][3] + bi1);
            }
        }
    }
    // ---- Q then K: stage [s][d] in smem (Ts overlays As), coalesced float4
    #pragma unroll
    for (int p = 0; p < 2; p++) {
        const float qs = (p == 0) ? QSCALE : 1.0f;
        #pragma unroll
        for (int i = 0; i < 2; i++) {
            int r0 = wm * 32 + i * 16 + gid;
            float bi0 = bp[p][r0], bi1 = bp[p][r0 + 8];
            #pragma unroll
            for (int j = 0; j < 4; j++) {
                int col = wn * 32 + j * 8 + 2 * tig;
                Ts[col][r0]         = (Cacc[p][i][j][0] + bi0) * qs;
                Ts[col + 1][r0]     = (Cacc[p][i][j][1] + bi0) * qs;
                Ts[col][r0 + 8]     = (Cacc[p][i][j][2] + bi1) * qs;
                Ts[col + 1][r0 + 8] = (Cacc[p][i][j][3] + bi1) * qs;
            }
        }
        __syncthreads();
        float* g = ((p == 0) ? g_q : g_k) + (size_t)bn * S_ * D_;
        #pragma unroll
        for (int r = 0; r < 8; r++) {
            int i4 = tid + r * 128;
            int ss = i4 >> 4, d4 = (i4 & 15) * 4;
            *(float4*)&g[(size_t)(s0 + ss) * D_ + d4] = *(const float4*)&Ts[ss][d4];
        }
        __syncthreads();
    }
}

// ===========================================================================
// Flash attention: Q frags in regs, P in regs, j-outer, unshifted exp2
// softmax (log2e folded into Q scale), cp.async double-buffered K/V.
// Smem 73728 B -> 2 CTAs/SM.  grid (18, 16), block 128.
// ===========================================================================
extern __shared__ float s_at[];

__global__ __launch_bounds__(128) void attn_kernel()
{
    float (*K0)[72] = (float (*)[72])(s_at);
    float (*V0)[72] = (float (*)[72])(s_at + 4608);
    float (*K1)[72] = (float (*)[72])(s_at + 9216);
    float (*V1)[72] = (float (*)[72])(s_at + 13824);
    float (*Qs)[72] = (float (*)[72])(s_at + 9216);   // overlaps buf1

    const int bn = blockIdx.y;
    const int b = bn >> 3, n = bn & 7;
    const int q0 = blockIdx.x * QT;
    const int tid = threadIdx.x;
    const int wid = tid >> 5, lane = tid & 31;
    const int gid = lane >> 2, tig = lane & 3;
    const int qr  = wid * 32;

    const float* Q = g_q + (size_t)bn * S_ * D_;  // [s][d] pre-scaled (log2e)
    const float* K = g_k + (size_t)bn * S_ * D_;  // [s][d]
    const float* V = g_v + (size_t)bn * D_ * S_;  // [d][s]

    const int ldrow = tid >> 4, ldseg = (tid & 15) * 4;
    const uint32_t sK0 = (uint32_t)__cvta_generic_to_shared(&K0[0][0]);
    const uint32_t sV0 = (uint32_t)__cvta_generic_to_shared(&V0[0][0]);
    const uint32_t sK1 = (uint32_t)__cvta_generic_to_shared(&K1[0][0]);
    const uint32_t sV1 = (uint32_t)__cvta_generic_to_shared(&V1[0][0]);

    auto load_kv_async = [&](int c, int buf) {
        uint32_t sk = buf ? sK1 : sK0;
        uint32_t sv = buf ? sV1 : sV0;
        int k0 = c * 64;
        #pragma unroll
        for (int r = 0; r < 8; r++) {
            int row = ldrow + r * 8;
            uint32_t off = (uint32_t)(row * 72 + ldseg) * 4;
            cpasync16(sk + off, &K[(size_t)(k0 + row) * D_ + ldseg]);
            cpasync16(sv + off, &V[(size_t)row * S_ + k0 + ldseg]);
        }
        CP_COMMIT();
    };

    load_kv_async(0, 0);
    #pragma unroll
    for (int r = 0; r < 16; r++) {
        int i4 = tid + r * 128;
        int row = i4 >> 4, seg = (i4 & 15) * 4;
        *(float4*)&Qs[row][seg] = *(const float4*)&Q[(size_t)(q0 + row) * D_ + seg];
    }
    CP_WAIT0();
    __syncthreads();

    float2 qlo[2][8], qhi[2][8];
    #pragma unroll
    for (int kk8 = 0; kk8 < 8; kk8++)
        #pragma unroll
        for (int i = 0; i < 2; i++) {
            int row = qr + i * 16 + gid;
            qlo[i][kk8] = *(const float2*)&Qs[row][kk8 * 8 + 2 * tig];
            qhi[i][kk8] = *(const float2*)&Qs[row + 8][kk8 * 8 + 2 * tig];
        }
    __syncthreads();              // everyone read Q; buf1 region free

    float sum[2][2] = {};
    float O[2][8][4] = {};

    for (int c = 0; c < NCH; c++) {
        const int cur = c & 1;
        if (c + 1 < NCH) load_kv_async(c + 1, cur ^ 1);

        float (*Ksc)[72] = cur ? K1 : K0;
        float (*Vsc)[72] = cur ? V1 : V0;

        #pragma unroll
        for (int j = 0; j < 8; j++) {
            float Sc[2][4] = {};
            #pragma unroll
            for (int kk8 = 0; kk8 < 8; kk8++) {
                float2 bb = *(const float2*)&Ksc[j * 8 + gid][kk8 * 8 + 2 * tig];
                #pragma unroll
                for (int i = 0; i < 2; i++)
                    mma_tf32(Sc[i], qlo[i][kk8].x, qhi[i][kk8].x,
                             qlo[i][kk8].y, qhi[i][kk8].y, bb.x, bb.y);
            }
            float e[2][4];
            #pragma unroll
            for (int i = 0; i < 2; i++) {
                e[i][0] = exp2f(Sc[i][0]);
                e[i][1] = exp2f(Sc[i][1]);
                e[i][2] = exp2f(Sc[i][2]);
                e[i][3] = exp2f(Sc[i][3]);
                sum[i][0] += e[i][0] + e[i][1];
                sum[i][1] += e[i][2] + e[i][3];
            }
            #pragma unroll
            for (int nn = 0; nn < 8; nn++) {
                float2 bb = *(const float2*)&Vsc[nn * 8 + gid][j * 8 + 2 * tig];
                #pragma unroll
                for (int i = 0; i < 2; i++)
                    mma_tf32(O[i][nn], e[i][0], e[i][2], e[i][1], e[i][3], bb.x, bb.y);
            }
        }
        CP_WAIT0();
        __syncthreads();
    }

    float inv[2][2];
    #pragma unroll
    for (int i = 0; i < 2; i++)
        #pragma unroll
        for (int h = 0; h < 2; h++) {
            float s = sum[i][h];
            s += __shfl_xor_sync(0xffffffffu, s, 1);
            s += __shfl_xor_sync(0xffffffffu, s, 2);
            inv[i][h] = 1.f / s;
        }

    float* A = g_attn + ((size_t)b * S_ + q0) * (NH * D_) + n * D_;
    #pragma unroll
    for (int i = 0; i < 2; i++) {
        int row0 = qr + i * 16 + gid;
        #pragma unroll
        for (int j = 0; j < 8; j++) {
            int col = j * 8 + 2 * tig;
            *(float2*)&A[(size_t)row0 * (NH * D_) + col] =
                make_float2(O[i][j][0] * inv[i][0], O[i][j][1] * inv[i][0]);
            *(float2*)&A[(size_t)(row0 + 8) * (NH * D_) + col] =
                make_float2(O[i][j][2] * inv[i][1], O[i][j][3] * inv[i][1]);
        }
    }
}

// ===========================================================================
// Output projection (double-buffered, unchanged from R15).
// ===========================================================================
__global__ __launch_bounds__(128) void oproj_kernel(
    const float* __restrict__ Wo, const float* __restrict__ bo,
    float* __restrict__ out)
{
    __shared__ float sbuf[10240];
    float (*Ts)[68] = (float (*)[68])sbuf;

    const int b  = blockIdx.z;
    const int c0 = blockIdx.y * 64;
    const int s0 = blockIdx.x * 64;

    const int tid = threadIdx.x;
    const int wid = tid >> 5, lane = tid & 31;
    const int gid = lane >> 2, tig = lane & 3;
    const int wm  = wid >> 1, wn = wid & 1;

    const float* A = g_attn + ((size_t)b * S_ + s0) * C_;

    auto fill = [&](int c, int buf) {
        float (*As)[40] = (float (*)[40])(sbuf + buf * 5120);
        float (*Bs)[40] = (float (*)[40])(sbuf + buf * 5120 + 2560);
        int j0 = c * 32;
        #pragma unroll
        for (int r = 0; r < 4; r++) {
            int i4 = tid + r * 128;
            int rr = i4 >> 3, j4 = (i4 & 7) * 4;
            float4 va = *(const float4*)&A[(size_t)rr * C_ + j0 + j4];
            As[rr][j4]     = tf32r(va.x); As[rr][j4 + 1] = tf32r(va.y);
            As[rr][j4 + 2] = tf32r(va.z); As[rr][j4 + 3] = tf32r(va.w);
            float4 vb = *(const float4*)&Wo[(size_t)(c0 + rr) * C_ + j0 + j4];
            Bs[rr][j4]     = tf32r(vb.x); Bs[rr][j4 + 1] = tf32r(vb.y);
            Bs[rr][j4 + 2] = tf32r(vb.z); Bs[rr][j4 + 3] = tf32r(vb.w);
        }
    };

    float Cacc[2][4][4] = {};

    fill(0, 0);
    __syncthreads();

    for (int c = 0; c < 16; c++) {
        const int cur = c & 1;
        if (c + 1 < 16) fill(c + 1, cur ^ 1);

        float (*As)[40] = (float (*)[40])(sbuf + cur * 5120);
        float (*Bs)[40] = (float (*)[40])(sbuf + cur * 5120 + 2560);

        #pragma unroll
        for (int kk = 0; kk < 32; kk += 8) {
            float2 alo[2], ahi[2];
            #pragma unroll
            for (int i = 0; i < 2; i++) {
                int row = wm * 32 + i * 16 + gid;
                alo[i] = *(const float2*)&As[row][kk + 2 * tig];
                ahi[i] = *(const float2*)&As[row + 8][kk + 2 * tig];
            }
            #pragma unroll
            for (int j = 0; j < 4; j++) {
                float2 bb = *(const float2*)&Bs[wn * 32 + j * 8 + gid][kk + 2 * tig];
                #pragma unroll
                for (int i = 0; i < 2; i++)
                    mma_tf32(Cacc[i][j], alo[i].x, ahi[i].x, alo[i].y, ahi[i].y, bb.x, bb.y);
            }
        }
        __syncthreads();
    }

    #pragma unroll
    for (int i = 0; i < 2; i++) {
        int r0 = wm * 32 + i * 16 + gid;
        #pragma unroll
        for (int j = 0; j < 4; j++) {
            int cl = wn * 32 + j * 8 + 2 * tig;
            float b0 = bo[c0 + cl], b1 = bo[c0 + cl + 1];
            Ts[cl][r0]         = Cacc[i][j][0] + b0;
            Ts[cl + 1][r0]     = Cacc[i][j][1] + b1;
            Ts[cl][r0 + 8]     = Cacc[i][j][2] + b0;
            Ts[cl + 1][r0 + 8] = Cacc[i][j][3] + b1;
        }
    }
    __syncthreads();
    float* ob = out + ((size_t)b * C_ + c0) * S_ + s0;
    #pragma unroll
    for (int r = 0; r < 8; r++) {
        int i4 = tid + r * 128;
        int cc = i4 >> 4, s4 = (i4 & 15) * 4;
        *(float4*)&ob[(size_t)cc * S_ + s4] = *(const float4*)&Ts[cc][s4];
    }
}

// ---------------------------------------------------------------------------
extern "C" void kernel_launch(void* const* d_in, const int* in_sizes, int n_in,
                              void* d_out, int out_size)
{
    const float* x  = (const float*)d_in[0];
    const float* Wq = (const float*)d_in[1];
    const float* bq = (const float*)d_in[2];
    const float* Wk = (const float*)d_in[3];
    const float* bk = (const float*)d_in[4];
    const float* Wv = (const float*)d_in[5];
    const float* bv = (const float*)d_in[6];
    const float* Wo = (const float*)d_in[7];
    const float* bo = (const float*)d_in[8];
    float* out = (float*)d_out;

    const int attn_smem = 18432 * sizeof(float);   // 73728
    cudaFuncSetAttribute(attn_kernel,
                         cudaFuncAttributeMaxDynamicSharedMemorySize, attn_smem);

    proj_kernel <<<dim3(S_ / 64, B_ * NH), 128>>>(x, Wq, bq, Wk, bk, Wv, bv);
    attn_kernel <<<dim3(S_ / QT, B_ * NH), 128, attn_smem>>>();
    oproj_kernel<<<dim3(S_ / 64, C_ / 64, B_), 128>>>(Wo, bo, out);
}